// round 2
// baseline (speedup 1.0000x reference)
#include <cuda_runtime.h>

#define BB 16
#define NN 4096
#define SS 512
#define NSAMP 32
#define PPOS (BB*SS*NSAMP)   // 262144 positions

// ---------------- device scratch (no allocation allowed) ----------------
__device__ float g_feat[6*PPOS];      //  6.3 MB  grouped features [c][p]
__device__ float g_x1[64*PPOS];       // 67 MB    layer1 raw conv out
__device__ float g_x2[64*PPOS];       // 67 MB    layer2 raw conv out
__device__ float g_x3[128*PPOS];      // 134 MB   layer3 raw conv out
__device__ float g_stats[512];        // per-layer channel sums / sumsq
__device__ float g_ab[512];           // per-layer BN scale(A)/shift(B)
__device__ float4 g_new[BB*SS];       // centroid x,y,z,|c|^2

// ---------------- f32x2 helpers ----------------
__device__ __forceinline__ unsigned long long fma2(unsigned long long a,
                                                   unsigned long long b,
                                                   unsigned long long c) {
    unsigned long long d;
    asm("fma.rn.f32x2 %0, %1, %2, %3;" : "=l"(d) : "l"(a), "l"(b), "l"(c));
    return d;
}
__device__ __forceinline__ unsigned long long pack2(float lo, float hi) {
    unsigned long long d;
    asm("mov.b64 %0, {%1, %2};" : "=l"(d) : "f"(lo), "f"(hi));
    return d;
}
__device__ __forceinline__ float2 unpack2(unsigned long long v) {
    float2 r;
    asm("mov.b64 {%0, %1}, %2;" : "=f"(r.x), "=f"(r.y) : "l"(v));
    return r;
}

// ---------------- kernels ----------------
__global__ void zero_kernel() { g_stats[threadIdx.x] = 0.0f; }

// Farthest point sampling: 1 CTA per batch, 1024 threads, 4 pts/thread.
__global__ __launch_bounds__(1024) void fps_kernel(const float* __restrict__ xyz,
                                                   float* __restrict__ out_newxyz)
{
    extern __shared__ float sh[];
    float* xs = sh; float* ys = sh + NN; float* zs = sh + 2*NN;
    __shared__ unsigned long long wkey[32];
    __shared__ unsigned long long bcast;
    const int b = blockIdx.x;
    const int t = threadIdx.x;
    const int lane = t & 31, wid = t >> 5;
    const float* X = xyz + b*3*NN;

    float px[4], py[4], pz[4], dist[4];
#pragma unroll
    for (int k = 0; k < 4; ++k) {
        int n = t + k*1024;
        px[k] = X[n]; py[k] = X[NN+n]; pz[k] = X[2*NN+n];
        xs[n] = px[k]; ys[n] = py[k]; zs[n] = pz[k];
        dist[k] = 1e10f;
    }
    __syncthreads();

    int far = 0;
    for (int s = 0; s < SS; ++s) {
        float cx = xs[far], cy = ys[far], cz = zs[far];
        if (t == 0) {
            out_newxyz[(b*3+0)*SS + s] = cx;
            out_newxyz[(b*3+1)*SS + s] = cy;
            out_newxyz[(b*3+2)*SS + s] = cz;
            float sn = fmaf(cz,cz,fmaf(cy,cy,cx*cx));
            g_new[b*SS+s] = make_float4(cx,cy,cz,sn);
        }
        float bd = -1.0f; int bi = 0;
#pragma unroll
        for (int k = 0; k < 4; ++k) {
            float dx = px[k]-cx, dy = py[k]-cy, dz = pz[k]-cz;
            float d = fmaf(dz,dz,fmaf(dy,dy,dx*dx));
            float nd = fminf(dist[k], d);
            dist[k] = nd;
            if (nd > bd) { bd = nd; bi = t + k*1024; }
        }
        // argmax with lowest-index tie-break (matches jnp.argmax)
        unsigned long long key = ((unsigned long long)__float_as_uint(bd) << 32)
                               | (unsigned long long)(0xFFFFFFFFu - (unsigned)bi);
#pragma unroll
        for (int off = 16; off; off >>= 1) {
            unsigned long long o = __shfl_down_sync(0xFFFFFFFFu, key, off);
            if (o > key) key = o;
        }
        if (lane == 0) wkey[wid] = key;
        __syncthreads();
        if (t < 32) {
            unsigned long long k2 = wkey[t];
#pragma unroll
            for (int off = 16; off; off >>= 1) {
                unsigned long long o = __shfl_down_sync(0xFFFFFFFFu, k2, off);
                if (o > k2) k2 = o;
            }
            if (t == 0) bcast = k2;
        }
        __syncthreads();
        far = (int)(0xFFFFFFFFu - (unsigned)bcast);
    }
}

// Ball query + gather + relative-feature build. One warp per (b,s) centroid.
__global__ __launch_bounds__(256) void group_kernel(const float* __restrict__ xyz,
                                                    const float* __restrict__ pts)
{
    __shared__ int sel[8][NSAMP];
    const int lane = threadIdx.x & 31, w = threadIdx.x >> 5;
    const int id = blockIdx.x*8 + w;          // (b*SS + s)
    const int b = id >> 9;
    const float4 c4 = g_new[id];
    const float* X = xyz + b*3*NN;
    const float* Q = pts + b*3*NN;
    const float R2 = (float)(0.4*0.4);

    int cnt = 0;
    for (int base = 0; base < NN && cnt < NSAMP; base += 32) {
        int n = base + lane;
        float x = X[n], y = X[NN+n], z = X[2*NN+n];
        float sx  = fmaf(z,z,fmaf(y,y,x*x));
        float dot = fmaf(z,c4.z,fmaf(y,c4.y,x*c4.x));
        float sq  = (c4.w + sx) - 2.0f*dot;
        bool pred = (sq <= R2);
        unsigned m = __ballot_sync(0xFFFFFFFFu, pred);
        if (pred) {
            int pos = cnt + __popc(m & ((1u << lane) - 1u));
            if (pos < NSAMP) sel[w][pos] = n;
        }
        cnt += __popc(m);
    }
    __syncwarp();
    int total = cnt < NSAMP ? cnt : NSAMP;
    int idx = sel[w][lane < total ? lane : 0];

    int p = id*NSAMP + lane;
    g_feat[0*PPOS+p] = X[idx]      - c4.x;
    g_feat[1*PPOS+p] = X[NN+idx]   - c4.y;
    g_feat[2*PPOS+p] = X[2*NN+idx] - c4.z;
    g_feat[3*PPOS+p] = Q[idx];
    g_feat[4*PPOS+p] = Q[NN+idx];
    g_feat[5*PPOS+p] = Q[2*NN+idx];
}

// Pointwise conv (GEMM, f32x2 packed) with fused BN-stat accumulation.
// Optionally applies previous layer's BN affine + ReLU to the input tile.
template<int CIN, int COUT, bool AFF>
__global__ __launch_bounds__(256) void mlp_kernel(const float* __restrict__ in,
                                                  const float* __restrict__ w,
                                                  const float* __restrict__ bias,
                                                  const float* __restrict__ ab,
                                                  float* __restrict__ out,
                                                  float* __restrict__ stats)
{
    extern __shared__ float sh[];
    unsigned long long* wdup = (unsigned long long*)sh;   // duplicated (w,w) pairs
    float* tile = (float*)(sh + COUT*CIN*2);              // [CIN][128] positions
    const int tid = threadIdx.x;

    for (int i = tid; i < COUT*CIN; i += 256) {
        float v = w[i];
        wdup[i] = pack2(v, v);
    }
    const int p0 = blockIdx.x * 128;
    for (int i = tid; i < CIN*128; i += 256) {
        int c = i >> 7, pp = i & 127;
        float v = in[c*PPOS + p0 + pp];
        if constexpr (AFF)
            v = fmaxf(fmaf(v, __ldg(&ab[c]), __ldg(&ab[CIN+c])), 0.0f);
        tile[i] = v;
    }
    __syncthreads();

    const int OPW = COUT/8;
    const int wid = tid >> 5, lane = tid & 31;
    const int ob = wid * OPW;
    unsigned long long a0[OPW], a1[OPW];
#pragma unroll
    for (int j = 0; j < OPW; ++j) {
        float bv = bias[ob+j];
        a0[j] = pack2(bv, bv);
        a1[j] = a0[j];
    }
#pragma unroll 8
    for (int c = 0; c < CIN; ++c) {
        ulonglong2 iv = *(const ulonglong2*)(tile + c*128 + lane*4);
#pragma unroll
        for (int j = 0; j < OPW; ++j) {
            unsigned long long wv = wdup[(ob+j)*CIN + c];
            a0[j] = fma2(wv, iv.x, a0[j]);
            a1[j] = fma2(wv, iv.y, a1[j]);
        }
    }
#pragma unroll
    for (int j = 0; j < OPW; ++j) {
        float2 v01 = unpack2(a0[j]);
        float2 v23 = unpack2(a1[j]);
        float4 ov = make_float4(v01.x, v01.y, v23.x, v23.y);
        *(float4*)(out + (ob+j)*PPOS + p0 + lane*4) = ov;
        float sm = (ov.x+ov.y)+(ov.z+ov.w);
        float sq = ov.x*ov.x + ov.y*ov.y + ov.z*ov.z + ov.w*ov.w;
#pragma unroll
        for (int off = 16; off; off >>= 1) {
            sm += __shfl_down_sync(0xFFFFFFFFu, sm, off);
            sq += __shfl_down_sync(0xFFFFFFFFu, sq, off);
        }
        if (lane == 0) {
            atomicAdd(&stats[ob+j], sm);
            atomicAdd(&stats[COUT+ob+j], sq);
        }
    }
}

// Fold BN (batch stats over all B*NS*S) + gamma/beta into scale A, shift B.
__global__ void bnparam_kernel(const float* __restrict__ stats,
                               const float* __restrict__ g,
                               const float* __restrict__ beta,
                               float* __restrict__ ab, int C)
{
    int o = threadIdx.x;
    if (o < C) {
        const float invP = 1.0f / (float)PPOS;
        float mean = stats[o] * invP;
        float var  = stats[C+o] * invP - mean*mean;
        float inv  = rsqrtf(var + 1e-5f);
        float A = g[o] * inv;
        ab[o]   = A;
        ab[C+o] = fmaf(-mean, A, beta[o]);
    }
}

// Apply layer-3 affine+ReLU and max over the 32 neighbors; write (B,128,S).
__global__ __launch_bounds__(256) void maxpool_kernel(float* __restrict__ out)
{
    int t = blockIdx.x*256 + threadIdx.x;       // = ((b*128)+o)*512 + s
    int o = (t >> 9) & 127;
    int b = t >> 16;
    int s = t & 511;
    float A  = __ldg(&g_ab[256 + o]);
    float Bv = __ldg(&g_ab[256 + 128 + o]);
    const float4* src = (const float4*)(g_x3 + (size_t)o*PPOS + (size_t)(b*SS + s)*NSAMP);
    float m = -3.4e38f;
#pragma unroll
    for (int i = 0; i < 8; ++i) {
        float4 v = src[i];
        m = fmaxf(m, fmaf(v.x, A, Bv));
        m = fmaxf(m, fmaf(v.y, A, Bv));
        m = fmaxf(m, fmaf(v.z, A, Bv));
        m = fmaxf(m, fmaf(v.w, A, Bv));
    }
    out[t] = fmaxf(m, 0.0f);   // ReLU commutes with max
}

// ---------------- launch ----------------
extern "C" void kernel_launch(void* const* d_in, const int* in_sizes, int n_in,
                              void* d_out, int out_size)
{
    const float* xyz = (const float*)d_in[0];
    const float* pts = (const float*)d_in[1];
    const float* w0  = (const float*)d_in[2];
    const float* b0  = (const float*)d_in[3];
    const float* gm0 = (const float*)d_in[4];
    const float* be0 = (const float*)d_in[5];
    const float* w1  = (const float*)d_in[6];
    const float* b1  = (const float*)d_in[7];
    const float* gm1 = (const float*)d_in[8];
    const float* be1 = (const float*)d_in[9];
    const float* w2  = (const float*)d_in[10];
    const float* b2  = (const float*)d_in[11];
    const float* gm2 = (const float*)d_in[12];
    const float* be2 = (const float*)d_in[13];
    float* out = (float*)d_out;

    float *pf, *px1, *px2, *px3, *pst, *pab;
    cudaGetSymbolAddress((void**)&pf,  g_feat);
    cudaGetSymbolAddress((void**)&px1, g_x1);
    cudaGetSymbolAddress((void**)&px2, g_x2);
    cudaGetSymbolAddress((void**)&px3, g_x3);
    cudaGetSymbolAddress((void**)&pst, g_stats);
    cudaGetSymbolAddress((void**)&pab, g_ab);

    cudaFuncSetAttribute(fps_kernel, cudaFuncAttributeMaxDynamicSharedMemorySize, 49152);
    cudaFuncSetAttribute(mlp_kernel<64,64,true>,  cudaFuncAttributeMaxDynamicSharedMemorySize, 65536);
    cudaFuncSetAttribute(mlp_kernel<64,128,true>, cudaFuncAttributeMaxDynamicSharedMemorySize, 98304);

    zero_kernel<<<1, 512>>>();
    fps_kernel<<<BB, 1024, 49152>>>(xyz, out);
    group_kernel<<<(BB*SS)/8, 256>>>(xyz, pts);

    mlp_kernel<6,64,false><<<PPOS/128, 256, 6144>>>(pf, w0, b0, nullptr, px1, pst);
    bnparam_kernel<<<1, 64>>>(pst, gm0, be0, pab, 64);

    mlp_kernel<64,64,true><<<PPOS/128, 256, 65536>>>(px1, w1, b1, pab, px2, pst + 128);
    bnparam_kernel<<<1, 64>>>(pst + 128, gm1, be1, pab + 128, 64);

    mlp_kernel<64,128,true><<<PPOS/128, 256, 98304>>>(px2, w2, b2, pab + 128, px3, pst + 256);
    bnparam_kernel<<<1, 128>>>(pst + 256, gm2, be2, pab + 256, 128);

    maxpool_kernel<<<(BB*128*SS)/256, 256>>>(out + BB*3*SS);
}

// round 3
// speedup vs baseline: 1.6307x; 1.6307x over previous
#include <cuda_runtime.h>

#define BB 16
#define NN 4096
#define SS 512
#define NSAMP 32
#define PPOS (BB*SS*NSAMP)   // 262144 positions
#define NGRP (BB*SS)         // 8192 (b,s) groups

// ---------------- device scratch ----------------
__device__ float g_feat[6*PPOS];        // grouped features [c][p]
__device__ float g_x2[64*PPOS];         // layer2 raw conv out (only big intermediate)
__device__ float g_pmax[128*NGRP];      // raw layer3 max over 32 neighbors [o][id]
__device__ float g_pmin[128*NGRP];      // raw layer3 min
__device__ float g_stats[384];          // [0..127] L2 sum/sumsq, [128..383] L3
__device__ float g_gram[48];            // [0..5] feat sums, [6..26] Gram upper-tri
__device__ float g_ab[512];             // A/B per layer: L1 [0..127], L2 [128..255], L3 [256..511]
__device__ float4 g_new[NGRP];          // centroid x,y,z,|c|^2

// ---------------- f32x2 helpers ----------------
__device__ __forceinline__ unsigned long long fma2(unsigned long long a,
                                                   unsigned long long b,
                                                   unsigned long long c) {
    unsigned long long d;
    asm("fma.rn.f32x2 %0, %1, %2, %3;" : "=l"(d) : "l"(a), "l"(b), "l"(c));
    return d;
}
__device__ __forceinline__ unsigned long long pack2(float lo, float hi) {
    unsigned long long d;
    asm("mov.b64 %0, {%1, %2};" : "=l"(d) : "f"(lo), "f"(hi));
    return d;
}
__device__ __forceinline__ float2 unpack2(unsigned long long v) {
    float2 r;
    asm("mov.b64 {%0, %1}, %2;" : "=f"(r.x), "=f"(r.y) : "l"(v));
    return r;
}

// ---------------- small kernels ----------------
__global__ void zero_kernel() {
    int t = threadIdx.x;
    if (t < 384) g_stats[t] = 0.0f;
    if (t < 48)  g_gram[t]  = 0.0f;
}

// Farthest point sampling: 1 CTA/batch, 512 threads, 8 pts/thread.
// redux.sync-based argmax with exact lowest-index tie-break.
__global__ __launch_bounds__(512) void fps_kernel(const float* __restrict__ xyz,
                                                  float* __restrict__ out_newxyz)
{
    extern __shared__ float sh[];
    float* xs = sh; float* ys = sh + NN; float* zs = sh + 2*NN;
    __shared__ unsigned long long wkey[16];
    __shared__ int s_far;
    const int b = blockIdx.x;
    const int t = threadIdx.x;
    const int lane = t & 31, wid = t >> 5;
    const float* X = xyz + b*3*NN;

    float px[8], py[8], pz[8], dist[8];
#pragma unroll
    for (int k = 0; k < 8; ++k) {
        int n = t + k*512;
        px[k] = X[n]; py[k] = X[NN+n]; pz[k] = X[2*NN+n];
        xs[n] = px[k]; ys[n] = py[k]; zs[n] = pz[k];
        dist[k] = 1e10f;
    }
    __syncthreads();

    int far = 0;
    for (int s = 0; s < SS; ++s) {
        float cx = xs[far], cy = ys[far], cz = zs[far];
        if (t == 0) {
            out_newxyz[(b*3+0)*SS + s] = cx;
            out_newxyz[(b*3+1)*SS + s] = cy;
            out_newxyz[(b*3+2)*SS + s] = cz;
            float sn = fmaf(cz,cz,fmaf(cy,cy,cx*cx));
            g_new[b*SS+s] = make_float4(cx,cy,cz,sn);
        }
        float bd = -1.0f; int bi = 0;
#pragma unroll
        for (int k = 0; k < 8; ++k) {
            float dx = px[k]-cx, dy = py[k]-cy, dz = pz[k]-cz;
            float d = fmaf(dz,dz,fmaf(dy,dy,dx*dx));
            float nd = fminf(dist[k], d);
            dist[k] = nd;
            if (nd > bd) { bd = nd; bi = t + k*512; }
        }
        // dist >= 0, so float bits are order-preserving as unsigned
        unsigned db = __float_as_uint(bd);
        unsigned wm = __reduce_max_sync(0xFFFFFFFFu, db);
        unsigned lo = __reduce_max_sync(0xFFFFFFFFu, (db == wm) ? ~(unsigned)bi : 0u);
        if (lane == 0) wkey[wid] = ((unsigned long long)wm << 32) | lo;
        __syncthreads();
        if (t < 32) {
            unsigned long long k2 = (t < 16) ? wkey[t] : 0ull;
            unsigned hi = (unsigned)(k2 >> 32), l2 = (unsigned)k2;
            unsigned m2 = __reduce_max_sync(0xFFFFFFFFu, hi);
            unsigned lw = __reduce_max_sync(0xFFFFFFFFu, (hi == m2) ? l2 : 0u);
            if (t == 0) s_far = (int)(~lw);
        }
        __syncthreads();
        far = s_far;
    }
}

// Ball query + gather. One warp per (b,s) centroid.
__global__ __launch_bounds__(256) void group_kernel(const float* __restrict__ xyz,
                                                    const float* __restrict__ pts)
{
    __shared__ int sel[8][NSAMP];
    const int lane = threadIdx.x & 31, w = threadIdx.x >> 5;
    const int id = blockIdx.x*8 + w;
    const int b = id >> 9;
    const float4 c4 = g_new[id];
    const float* X = xyz + b*3*NN;
    const float* Q = pts + b*3*NN;
    const float R2 = (float)(0.4*0.4);

    int cnt = 0;
    for (int base = 0; base < NN && cnt < NSAMP; base += 32) {
        int n = base + lane;
        float x = X[n], y = X[NN+n], z = X[2*NN+n];
        float sx  = fmaf(z,z,fmaf(y,y,x*x));
        float dot = fmaf(z,c4.z,fmaf(y,c4.y,x*c4.x));
        float sq  = (c4.w + sx) - 2.0f*dot;
        bool pred = (sq <= R2);
        unsigned m = __ballot_sync(0xFFFFFFFFu, pred);
        if (pred) {
            int pos = cnt + __popc(m & ((1u << lane) - 1u));
            if (pos < NSAMP) sel[w][pos] = n;
        }
        cnt += __popc(m);
    }
    __syncwarp();
    int total = cnt < NSAMP ? cnt : NSAMP;
    int idx = sel[w][lane < total ? lane : 0];

    int p = id*NSAMP + lane;
    g_feat[0*PPOS+p] = X[idx]      - c4.x;
    g_feat[1*PPOS+p] = X[NN+idx]   - c4.y;
    g_feat[2*PPOS+p] = X[2*NN+idx] - c4.z;
    g_feat[3*PPOS+p] = Q[idx];
    g_feat[4*PPOS+p] = Q[NN+idx];
    g_feat[5*PPOS+p] = Q[2*NN+idx];
}

// Channel sums + 6x6 Gram of grouped features (for analytic BN1 stats).
__global__ __launch_bounds__(256) void gram_kernel()
{
    const int lane = threadIdx.x & 31;
    float s[6]  = {0,0,0,0,0,0};
    float g[21];
#pragma unroll
    for (int i = 0; i < 21; ++i) g[i] = 0.0f;

    int base = blockIdx.x*2048 + threadIdx.x;
#pragma unroll
    for (int k = 0; k < 8; ++k) {
        int p = base + k*256;
        float f[6];
#pragma unroll
        for (int c = 0; c < 6; ++c) f[c] = g_feat[c*PPOS + p];
#pragma unroll
        for (int c = 0; c < 6; ++c) s[c] += f[c];
        int idx = 0;
#pragma unroll
        for (int i = 0; i < 6; ++i)
#pragma unroll
            for (int j = i; j < 6; ++j) g[idx++] = fmaf(f[i], f[j], g[idx]);
    }
#pragma unroll
    for (int off = 16; off; off >>= 1) {
#pragma unroll
        for (int c = 0; c < 6; ++c)  s[c] += __shfl_down_sync(0xFFFFFFFFu, s[c], off);
#pragma unroll
        for (int i = 0; i < 21; ++i) g[i] += __shfl_down_sync(0xFFFFFFFFu, g[i], off);
    }
    if (lane == 0) {
#pragma unroll
        for (int c = 0; c < 6; ++c)  atomicAdd(&g_gram[c], s[c]);
#pragma unroll
        for (int i = 0; i < 21; ++i) atomicAdd(&g_gram[6+i], g[i]);
    }
}

// Analytic BN1: stats of x1 = W0 f + b0 from sums + Gram; fold bias into B.
__global__ void bn1param_kernel(const float* __restrict__ w0,
                                const float* __restrict__ b0,
                                const float* __restrict__ g0,
                                const float* __restrict__ beta0)
{
    int o = threadIdx.x;
    if (o >= 64) return;
    float w[6], S[6];
#pragma unroll
    for (int c = 0; c < 6; ++c) { w[c] = w0[o*6+c]; S[c] = g_gram[c]; }
    float wS = 0.0f;
#pragma unroll
    for (int c = 0; c < 6; ++c) wS = fmaf(w[c], S[c], wS);
    float quad = 0.0f; int idx = 6;
#pragma unroll
    for (int i = 0; i < 6; ++i)
#pragma unroll
        for (int j = i; j < 6; ++j) {
            float coef = (i == j) ? 1.0f : 2.0f;
            quad = fmaf(coef * w[i] * w[j], g_gram[idx++], quad);
        }
    float bo = b0[o];
    const float invP = 1.0f / (float)PPOS;
    float m   = fmaf(wS, invP, bo);
    float Ex2 = quad*invP + 2.0f*bo*wS*invP + bo*bo;
    float var = Ex2 - m*m;
    float A = g0[o] * rsqrtf(var + 1e-5f);
    g_ab[o]    = A;
    g_ab[64+o] = fmaf(bo - m, A, beta0[o]);   // relu(A*raw + B), raw = W0 f (no bias)
}

// Fused layer1+layer2: feat -> x1 (smem only, BN1+relu) -> x2 (global, raw) + BN2 stats.
__global__ __launch_bounds__(256,2) void fused12_kernel(const float* __restrict__ w0,
                                                        const float* __restrict__ w1,
                                                        const float* __restrict__ b1)
{
    extern __shared__ char smraw[];
    unsigned long long* w0d = (unsigned long long*)smraw;            // 384 ull
    unsigned long long* w1d = (unsigned long long*)(smraw + 3072);   // 4096 ull
    float* tf = (float*)(smraw + 35840);                             // 6 x 256
    float* tx = (float*)(smraw + 41984);                             // 64 x 256
    const int tid  = threadIdx.x;
    const int lane = tid & 31, wid = tid >> 5;
    const int ob = wid * 8;
    const int p0 = blockIdx.x * 256;

    for (int i = tid; i < 384;  i += 256) { float v = w0[i]; w0d[i] = pack2(v,v); }
    for (int i = tid; i < 4096; i += 256) { float v = w1[i]; w1d[i] = pack2(v,v); }
    for (int i = tid; i < 1536; i += 256) {
        int c = i >> 8, pp = i & 255;
        tf[i] = g_feat[c*PPOS + p0 + pp];
    }
    __syncthreads();

    // ---- stage A: 6 -> 64 ----
    {
        unsigned long long a[8][4];
#pragma unroll
        for (int j = 0; j < 8; ++j)
#pragma unroll
            for (int q = 0; q < 4; ++q) a[j][q] = 0ull;
#pragma unroll
        for (int c = 0; c < 6; ++c) {
            ulonglong2 iv0 = *(const ulonglong2*)(tf + c*256 + lane*4);
            ulonglong2 iv1 = *(const ulonglong2*)(tf + c*256 + 128 + lane*4);
#pragma unroll
            for (int j = 0; j < 8; ++j) {
                unsigned long long wv = w0d[(ob+j)*6 + c];
                a[j][0] = fma2(wv, iv0.x, a[j][0]);
                a[j][1] = fma2(wv, iv0.y, a[j][1]);
                a[j][2] = fma2(wv, iv1.x, a[j][2]);
                a[j][3] = fma2(wv, iv1.y, a[j][3]);
            }
        }
#pragma unroll
        for (int j = 0; j < 8; ++j) {
            float A = g_ab[ob+j], Bv = g_ab[64+ob+j];
#pragma unroll
            for (int s2 = 0; s2 < 2; ++s2) {
                float2 u = unpack2(a[j][s2*2+0]);
                float2 v = unpack2(a[j][s2*2+1]);
                float4 o4;
                o4.x = fmaxf(fmaf(u.x,A,Bv),0.f);
                o4.y = fmaxf(fmaf(u.y,A,Bv),0.f);
                o4.z = fmaxf(fmaf(v.x,A,Bv),0.f);
                o4.w = fmaxf(fmaf(v.y,A,Bv),0.f);
                *(float4*)(tx + (ob+j)*256 + s2*128 + lane*4) = o4;
            }
        }
    }
    __syncthreads();

    // ---- stage B: 64 -> 64 ----
    unsigned long long acc[8][4];
#pragma unroll
    for (int j = 0; j < 8; ++j) {
        float bv = b1[ob+j];
        unsigned long long pb = pack2(bv,bv);
#pragma unroll
        for (int q = 0; q < 4; ++q) acc[j][q] = pb;
    }
#pragma unroll 4
    for (int c2 = 0; c2 < 32; ++c2) {
        const float* base = tx + c2*512;
        ulonglong2 a0 = *(const ulonglong2*)(base + lane*4);
        ulonglong2 a1 = *(const ulonglong2*)(base + 128 + lane*4);
        ulonglong2 c0 = *(const ulonglong2*)(base + 256 + lane*4);
        ulonglong2 c1 = *(const ulonglong2*)(base + 384 + lane*4);
#pragma unroll
        for (int j = 0; j < 8; ++j) {
            ulonglong2 wp = *(const ulonglong2*)(w1d + (ob+j)*64 + c2*2);
            acc[j][0] = fma2(wp.x, a0.x, acc[j][0]);
            acc[j][1] = fma2(wp.x, a0.y, acc[j][1]);
            acc[j][2] = fma2(wp.x, a1.x, acc[j][2]);
            acc[j][3] = fma2(wp.x, a1.y, acc[j][3]);
            acc[j][0] = fma2(wp.y, c0.x, acc[j][0]);
            acc[j][1] = fma2(wp.y, c0.y, acc[j][1]);
            acc[j][2] = fma2(wp.y, c1.x, acc[j][2]);
            acc[j][3] = fma2(wp.y, c1.y, acc[j][3]);
        }
    }
#pragma unroll
    for (int j = 0; j < 8; ++j) {
        float2 u0 = unpack2(acc[j][0]), u1 = unpack2(acc[j][1]);
        float2 v0 = unpack2(acc[j][2]), v1 = unpack2(acc[j][3]);
        float4 o0 = make_float4(u0.x,u0.y,u1.x,u1.y);
        float4 o1 = make_float4(v0.x,v0.y,v1.x,v1.y);
        *(float4*)(g_x2 + (size_t)(ob+j)*PPOS + p0 + lane*4)       = o0;
        *(float4*)(g_x2 + (size_t)(ob+j)*PPOS + p0 + 128 + lane*4) = o1;
        float sm1 = ((o0.x+o0.y)+(o0.z+o0.w)) + ((o1.x+o1.y)+(o1.z+o1.w));
        float sq  = o0.x*o0.x+o0.y*o0.y+o0.z*o0.z+o0.w*o0.w
                  + o1.x*o1.x+o1.y*o1.y+o1.z*o1.z+o1.w*o1.w;
#pragma unroll
        for (int off = 16; off; off >>= 1) {
            sm1 += __shfl_down_sync(0xFFFFFFFFu, sm1, off);
            sq  += __shfl_down_sync(0xFFFFFFFFu, sq,  off);
        }
        if (lane == 0) {
            atomicAdd(&g_stats[ob+j],    sm1);
            atomicAdd(&g_stats[64+ob+j], sq);
        }
    }
}

// Generic BN fold: A = g*rsqrt(var+eps), B = beta - mean*A.
__global__ void bnparam_kernel(const float* __restrict__ stats,
                               const float* __restrict__ g,
                               const float* __restrict__ beta,
                               float* __restrict__ ab, int C)
{
    int o = threadIdx.x;
    if (o < C) {
        const float invP = 1.0f / (float)PPOS;
        float mean = stats[o]   * invP;
        float var  = stats[C+o] * invP - mean*mean;
        float A = g[o] * rsqrtf(var + 1e-5f);
        ab[o]   = A;
        ab[C+o] = fmaf(-mean, A, beta[o]);
    }
}

// Layer3 (64->128) with fused BN3 stats + raw max/min pooling over 32 neighbors.
__global__ __launch_bounds__(512) void mlp3_kernel(const float* __restrict__ w2,
                                                   const float* __restrict__ b2)
{
    extern __shared__ char smraw[];
    unsigned long long* wd = (unsigned long long*)smraw;   // 8192 ull = 64KB
    float* tx = (float*)(smraw + 65536);                   // 64 x 256 = 64KB
    const int tid  = threadIdx.x;
    const int lane = tid & 31, wid = tid >> 5;
    const int ob = wid * 8;
    const int p0 = blockIdx.x * 256;

    for (int i = tid; i < 8192; i += 512) { float v = w2[i]; wd[i] = pack2(v,v); }
    for (int i = tid; i < 16384; i += 512) {
        int c = i >> 8, pp = i & 255;
        float A = g_ab[128+c], Bv = g_ab[192+c];
        tx[i] = fmaxf(fmaf(g_x2[(size_t)c*PPOS + p0 + pp], A, Bv), 0.0f);
    }
    __syncthreads();

    unsigned long long acc[8][4];
#pragma unroll
    for (int j = 0; j < 8; ++j) {
        float bv = b2[ob+j];
        unsigned long long pb = pack2(bv,bv);
#pragma unroll
        for (int q = 0; q < 4; ++q) acc[j][q] = pb;
    }
#pragma unroll 4
    for (int c2 = 0; c2 < 32; ++c2) {
        const float* base = tx + c2*512;
        ulonglong2 a0 = *(const ulonglong2*)(base + lane*4);
        ulonglong2 a1 = *(const ulonglong2*)(base + 128 + lane*4);
        ulonglong2 c0 = *(const ulonglong2*)(base + 256 + lane*4);
        ulonglong2 c1 = *(const ulonglong2*)(base + 384 + lane*4);
#pragma unroll
        for (int j = 0; j < 8; ++j) {
            ulonglong2 wp = *(const ulonglong2*)(wd + (ob+j)*64 + c2*2);
            acc[j][0] = fma2(wp.x, a0.x, acc[j][0]);
            acc[j][1] = fma2(wp.x, a0.y, acc[j][1]);
            acc[j][2] = fma2(wp.x, a1.x, acc[j][2]);
            acc[j][3] = fma2(wp.x, a1.y, acc[j][3]);
            acc[j][0] = fma2(wp.y, c0.x, acc[j][0]);
            acc[j][1] = fma2(wp.y, c0.y, acc[j][1]);
            acc[j][2] = fma2(wp.y, c1.x, acc[j][2]);
            acc[j][3] = fma2(wp.y, c1.y, acc[j][3]);
        }
    }
#pragma unroll
    for (int j = 0; j < 8; ++j) {
        float2 u0 = unpack2(acc[j][0]), u1 = unpack2(acc[j][1]);
        float2 v0 = unpack2(acc[j][2]), v1 = unpack2(acc[j][3]);
        float f0 = u0.x, f1 = u0.y, f2 = u1.x, f3 = u1.y;   // s=0 positions
        float f4 = v0.x, f5 = v0.y, f6 = v1.x, f7 = v1.y;   // s=1 positions
        // BN3 stats
        float sm1 = ((f0+f1)+(f2+f3)) + ((f4+f5)+(f6+f7));
        float sq  = f0*f0+f1*f1+f2*f2+f3*f3 + f4*f4+f5*f5+f6*f6+f7*f7;
#pragma unroll
        for (int off = 16; off; off >>= 1) {
            sm1 += __shfl_down_sync(0xFFFFFFFFu, sm1, off);
            sq  += __shfl_down_sync(0xFFFFFFFFu, sq,  off);
        }
        if (lane == 0) {
            atomicAdd(&g_stats[128+ob+j], sm1);
            atomicAdd(&g_stats[256+ob+j], sq);
        }
        // raw max/min over each 32-neighbor group (8 lanes x 4 positions)
#pragma unroll
        for (int s2 = 0; s2 < 2; ++s2) {
            float a = s2 ? f4 : f0, b = s2 ? f5 : f1, c = s2 ? f6 : f2, d = s2 ? f7 : f3;
            float mx = fmaxf(fmaxf(a,b), fmaxf(c,d));
            float mn = fminf(fminf(a,b), fminf(c,d));
#pragma unroll
            for (int dlt = 1; dlt < 8; dlt <<= 1) {
                mx = fmaxf(mx, __shfl_xor_sync(0xFFFFFFFFu, mx, dlt));
                mn = fminf(mn, __shfl_xor_sync(0xFFFFFFFFu, mn, dlt));
            }
            if ((lane & 7) == 0) {
                int gid = blockIdx.x*8 + s2*4 + (lane >> 3);
                g_pmax[(ob+j)*NGRP + gid] = mx;
                g_pmin[(ob+j)*NGRP + gid] = mn;
            }
        }
    }
}

// Final: affine3+relu applied to pooled max (or min if A<0). out[b][o][s].
__global__ __launch_bounds__(256) void final_kernel(float* __restrict__ out)
{
    int t = blockIdx.x*256 + threadIdx.x;
    int o = (t >> 9) & 127;
    int b = t >> 16;
    int s = t & 511;
    int gid = b*512 + s;
    float A  = g_ab[256 + o];
    float Bv = g_ab[384 + o];
    float v = (A >= 0.0f) ? g_pmax[o*NGRP + gid] : g_pmin[o*NGRP + gid];
    out[t] = fmaxf(fmaf(v, A, Bv), 0.0f);
}

// ---------------- launch ----------------
extern "C" void kernel_launch(void* const* d_in, const int* in_sizes, int n_in,
                              void* d_out, int out_size)
{
    const float* xyz = (const float*)d_in[0];
    const float* pts = (const float*)d_in[1];
    const float* w0  = (const float*)d_in[2];
    const float* b0  = (const float*)d_in[3];
    const float* gm0 = (const float*)d_in[4];
    const float* be0 = (const float*)d_in[5];
    const float* w1  = (const float*)d_in[6];
    const float* b1  = (const float*)d_in[7];
    const float* gm1 = (const float*)d_in[8];
    const float* be1 = (const float*)d_in[9];
    const float* w2  = (const float*)d_in[10];
    const float* b2  = (const float*)d_in[11];
    const float* gm2 = (const float*)d_in[12];
    const float* be2 = (const float*)d_in[13];
    float* out = (float*)d_out;

    float *pst, *pab;
    cudaGetSymbolAddress((void**)&pst, g_stats);
    cudaGetSymbolAddress((void**)&pab, g_ab);

    cudaFuncSetAttribute(fps_kernel,     cudaFuncAttributeMaxDynamicSharedMemorySize, 49152);
    cudaFuncSetAttribute(fused12_kernel, cudaFuncAttributeMaxDynamicSharedMemorySize, 107520);
    cudaFuncSetAttribute(mlp3_kernel,    cudaFuncAttributeMaxDynamicSharedMemorySize, 131072);

    zero_kernel<<<1, 512>>>();
    fps_kernel<<<BB, 512, 49152>>>(xyz, out);
    group_kernel<<<(BB*SS)/8, 256>>>(xyz, pts);
    gram_kernel<<<128, 256>>>();
    bn1param_kernel<<<1, 64>>>(w0, b0, gm0, be0);

    fused12_kernel<<<PPOS/256, 256, 107520>>>(w0, w1, b1);
    bnparam_kernel<<<1, 64>>>(pst, gm1, be1, pab + 128, 64);

    mlp3_kernel<<<PPOS/256, 512, 131072>>>(w2, b2);
    bnparam_kernel<<<1, 128>>>(pst + 128, gm2, be2, pab + 256, 128);

    final_kernel<<<(BB*128*SS)/256, 256>>>(out + BB*3*SS);
}

// round 4
// speedup vs baseline: 1.6982x; 1.0414x over previous
#include <cuda_runtime.h>

#define BB 16
#define NN 4096
#define SS 512
#define NSAMP 32
#define PPOS (BB*SS*NSAMP)   // 262144 positions
#define NGRP (BB*SS)         // 8192 (b,s) groups

// ---------------- device scratch ----------------
__device__ float g_feat[6*PPOS];        // grouped features [c][p]
__device__ float g_x2[64*PPOS];         // layer2 raw conv out
__device__ float g_pmax[128*NGRP];      // raw layer3 max over 32 neighbors [o][id]
__device__ float g_pmin[128*NGRP];      // raw layer3 min
__device__ float g_stats[384];          // [0..127] L2 sum/sumsq, [128..383] L3
__device__ float g_gram[27*32];         // 27 moments, each padded to own 128B line
__device__ float g_ab[512];             // A/B: L1 [0..127], L2 [128..255], L3 [256..511]
__device__ float4 g_new[NGRP];          // centroid x,y,z,|c|^2

// ---------------- f32x2 helpers ----------------
__device__ __forceinline__ unsigned long long fma2(unsigned long long a,
                                                   unsigned long long b,
                                                   unsigned long long c) {
    unsigned long long d;
    asm("fma.rn.f32x2 %0, %1, %2, %3;" : "=l"(d) : "l"(a), "l"(b), "l"(c));
    return d;
}
__device__ __forceinline__ unsigned long long pack2(float lo, float hi) {
    unsigned long long d;
    asm("mov.b64 %0, {%1, %2};" : "=l"(d) : "f"(lo), "f"(hi));
    return d;
}
__device__ __forceinline__ float2 unpack2(unsigned long long v) {
    float2 r;
    asm("mov.b64 {%0, %1}, %2;" : "=f"(r.x), "=f"(r.y) : "l"(v));
    return r;
}

// Farthest point sampling: 1 CTA/batch, 512 threads, 8 pts/thread.
// One barrier per iteration: double-buffered warp keys + redundant all-warp reduce.
__global__ __launch_bounds__(512) void fps_kernel(const float* __restrict__ xyz,
                                                  float* __restrict__ out_newxyz)
{
    extern __shared__ float sh[];
    float* xs = sh; float* ys = sh + NN; float* zs = sh + 2*NN;
    __shared__ unsigned long long wkey[2][16];
    const int b = blockIdx.x;
    const int t = threadIdx.x;
    const int lane = t & 31, wid = t >> 5;
    const float* X = xyz + b*3*NN;

    if (b == 0) {   // fold stat zeroing into this kernel (completes before group runs)
        for (int i = t; i < 384;   i += 512) g_stats[i] = 0.0f;
        for (int i = t; i < 27*32; i += 512) g_gram[i]  = 0.0f;
    }

    float px[8], py[8], pz[8], dist[8];
#pragma unroll
    for (int k = 0; k < 8; ++k) {
        int n = t + k*512;
        px[k] = X[n]; py[k] = X[NN+n]; pz[k] = X[2*NN+n];
        xs[n] = px[k]; ys[n] = py[k]; zs[n] = pz[k];
        dist[k] = 1e10f;
    }
    __syncthreads();

    int far = 0;
    for (int s = 0; s < SS; ++s) {
        float cx = xs[far], cy = ys[far], cz = zs[far];
        if (t == 0) {
            out_newxyz[(b*3+0)*SS + s] = cx;
            out_newxyz[(b*3+1)*SS + s] = cy;
            out_newxyz[(b*3+2)*SS + s] = cz;
            float sn = fmaf(cz,cz,fmaf(cy,cy,cx*cx));
            g_new[b*SS+s] = make_float4(cx,cy,cz,sn);
        }
        float bd = -1.0f; int bi = 0;
#pragma unroll
        for (int k = 0; k < 8; ++k) {
            float dx = px[k]-cx, dy = py[k]-cy, dz = pz[k]-cz;
            float d = fmaf(dz,dz,fmaf(dy,dy,dx*dx));
            float nd = fminf(dist[k], d);
            dist[k] = nd;
            if (nd > bd) { bd = nd; bi = t + k*512; }
        }
        // dist >= 0: float bits order-preserving as unsigned
        unsigned db = __float_as_uint(bd);
        unsigned wm = __reduce_max_sync(0xFFFFFFFFu, db);
        unsigned lo = __reduce_max_sync(0xFFFFFFFFu, (db == wm) ? ~(unsigned)bi : 0u);
        if (lane == 0) wkey[s & 1][wid] = ((unsigned long long)wm << 32) | lo;
        __syncthreads();
        // every warp redundantly reduces the 16 warp keys (no 2nd barrier needed:
        // next iter writes the other buffer)
        unsigned long long k2 = (lane < 16) ? wkey[s & 1][lane] : 0ull;
        unsigned hi = (unsigned)(k2 >> 32), l2 = (unsigned)k2;
        unsigned m2 = __reduce_max_sync(0xFFFFFFFFu, hi);
        unsigned lw = __reduce_max_sync(0xFFFFFFFFu, (hi == m2) ? l2 : 0u);
        far = (int)(~lw);
    }
}

// Ball query + gather + fused Gram/channel-sum accumulation.
// One warp per (b,s) centroid; 8 warps per CTA.
__global__ __launch_bounds__(256) void group_kernel(const float* __restrict__ xyz,
                                                    const float* __restrict__ pts)
{
    __shared__ int sel[8][NSAMP];
    __shared__ float red[27];
    const int lane = threadIdx.x & 31, w = threadIdx.x >> 5;
    const int tid = threadIdx.x;
    if (tid < 27) red[tid] = 0.0f;
    __syncthreads();

    const int id = blockIdx.x*8 + w;
    const int b = id >> 9;
    const float4 c4 = g_new[id];
    const float* X = xyz + b*3*NN;
    const float* Q = pts + b*3*NN;
    const float R2 = (float)(0.4*0.4);

    int cnt = 0;
    for (int base = 0; base < NN && cnt < NSAMP; base += 32) {
        int n = base + lane;
        float x = X[n], y = X[NN+n], z = X[2*NN+n];
        float sx  = fmaf(z,z,fmaf(y,y,x*x));
        float dot = fmaf(z,c4.z,fmaf(y,c4.y,x*c4.x));
        float sq  = (c4.w + sx) - 2.0f*dot;
        bool pred = (sq <= R2);
        unsigned m = __ballot_sync(0xFFFFFFFFu, pred);
        if (pred) {
            int pos = cnt + __popc(m & ((1u << lane) - 1u));
            if (pos < NSAMP) sel[w][pos] = n;
        }
        cnt += __popc(m);
    }
    __syncwarp();
    int total = cnt < NSAMP ? cnt : NSAMP;
    int idx = sel[w][lane < total ? lane : 0];

    float f[6];
    f[0] = X[idx]      - c4.x;
    f[1] = X[NN+idx]   - c4.y;
    f[2] = X[2*NN+idx] - c4.z;
    f[3] = Q[idx];
    f[4] = Q[NN+idx];
    f[5] = Q[2*NN+idx];

    int p = id*NSAMP + lane;
#pragma unroll
    for (int c = 0; c < 6; ++c) g_feat[c*PPOS + p] = f[c];

    // moments: 6 sums + 21 upper-tri products, reduced over the warp's 32 positions
    float v[27];
#pragma unroll
    for (int c = 0; c < 6; ++c) v[c] = f[c];
    {
        int k = 6;
#pragma unroll
        for (int i = 0; i < 6; ++i)
#pragma unroll
            for (int j = i; j < 6; ++j) { v[k] = f[i]*f[j]; ++k; }
    }
#pragma unroll
    for (int off = 16; off; off >>= 1)
#pragma unroll
        for (int i = 0; i < 27; ++i)
            v[i] += __shfl_down_sync(0xFFFFFFFFu, v[i], off);
    if (lane == 0)
#pragma unroll
        for (int i = 0; i < 27; ++i) atomicAdd(&red[i], v[i]);
    __syncthreads();
    if (tid < 27) atomicAdd(&g_gram[tid*32], red[tid]);
}

// Analytic BN1: stats of x1 = W0 f + b0 from sums + Gram; fold bias into B.
__global__ void bn1param_kernel(const float* __restrict__ w0,
                                const float* __restrict__ b0,
                                const float* __restrict__ g0,
                                const float* __restrict__ beta0)
{
    int o = threadIdx.x;
    if (o >= 64) return;
    float w[6], S[6];
#pragma unroll
    for (int c = 0; c < 6; ++c) { w[c] = w0[o*6+c]; S[c] = g_gram[c*32]; }
    float wS = 0.0f;
#pragma unroll
    for (int c = 0; c < 6; ++c) wS = fmaf(w[c], S[c], wS);
    float quad = 0.0f; int idx = 6;
#pragma unroll
    for (int i = 0; i < 6; ++i)
#pragma unroll
        for (int j = i; j < 6; ++j) {
            float coef = (i == j) ? 1.0f : 2.0f;
            quad = fmaf(coef * w[i] * w[j], g_gram[idx*32], quad);
            ++idx;
        }
    float bo = b0[o];
    const float invP = 1.0f / (float)PPOS;
    float m   = fmaf(wS, invP, bo);
    float Ex2 = quad*invP + 2.0f*bo*wS*invP + bo*bo;
    float var = Ex2 - m*m;
    float A = g0[o] * rsqrtf(var + 1e-5f);
    g_ab[o]    = A;
    g_ab[64+o] = fmaf(bo - m, A, beta0[o]);
}

// Fused layer1+layer2: feat -> x1 (smem, BN1+relu) -> x2 (global, raw) + BN2 stats.
__global__ __launch_bounds__(256,2) void fused12_kernel(const float* __restrict__ w0,
                                                        const float* __restrict__ w1,
                                                        const float* __restrict__ b1)
{
    extern __shared__ char smraw[];
    unsigned long long* w0d = (unsigned long long*)smraw;            // 384 ull
    unsigned long long* w1d = (unsigned long long*)(smraw + 3072);   // 4096 ull
    float* tf = (float*)(smraw + 35840);                             // 6 x 256
    float* tx = (float*)(smraw + 41984);                             // 64 x 256
    const int tid  = threadIdx.x;
    const int lane = tid & 31, wid = tid >> 5;
    const int ob = wid * 8;
    const int p0 = blockIdx.x * 256;

    for (int i = tid; i < 384; i += 256) { float v = w0[i]; w0d[i] = pack2(v,v); }
    for (int i = tid; i < 1024; i += 256) {
        float4 v = ((const float4*)w1)[i];
        w1d[i*4+0] = pack2(v.x,v.x); w1d[i*4+1] = pack2(v.y,v.y);
        w1d[i*4+2] = pack2(v.z,v.z); w1d[i*4+3] = pack2(v.w,v.w);
    }
    for (int i = tid; i < 384; i += 256) {
        int c = i >> 6, pp = (i & 63) * 4;
        *(float4*)(tf + c*256 + pp) = *(const float4*)(g_feat + c*PPOS + p0 + pp);
    }
    __syncthreads();

    // ---- stage A: 6 -> 64 ----
    {
        unsigned long long a[8][4];
#pragma unroll
        for (int j = 0; j < 8; ++j)
#pragma unroll
            for (int q = 0; q < 4; ++q) a[j][q] = 0ull;
#pragma unroll
        for (int c = 0; c < 6; ++c) {
            ulonglong2 iv0 = *(const ulonglong2*)(tf + c*256 + lane*4);
            ulonglong2 iv1 = *(const ulonglong2*)(tf + c*256 + 128 + lane*4);
#pragma unroll
            for (int j = 0; j < 8; ++j) {
                unsigned long long wv = w0d[(ob+j)*6 + c];
                a[j][0] = fma2(wv, iv0.x, a[j][0]);
                a[j][1] = fma2(wv, iv0.y, a[j][1]);
                a[j][2] = fma2(wv, iv1.x, a[j][2]);
                a[j][3] = fma2(wv, iv1.y, a[j][3]);
            }
        }
#pragma unroll
        for (int j = 0; j < 8; ++j) {
            float A = g_ab[ob+j], Bv = g_ab[64+ob+j];
#pragma unroll
            for (int s2 = 0; s2 < 2; ++s2) {
                float2 u = unpack2(a[j][s2*2+0]);
                float2 v = unpack2(a[j][s2*2+1]);
                float4 o4;
                o4.x = fmaxf(fmaf(u.x,A,Bv),0.f);
                o4.y = fmaxf(fmaf(u.y,A,Bv),0.f);
                o4.z = fmaxf(fmaf(v.x,A,Bv),0.f);
                o4.w = fmaxf(fmaf(v.y,A,Bv),0.f);
                *(float4*)(tx + (ob+j)*256 + s2*128 + lane*4) = o4;
            }
        }
    }
    __syncthreads();

    // ---- stage B: 64 -> 64 ----
    unsigned long long acc[8][4];
#pragma unroll
    for (int j = 0; j < 8; ++j) {
        float bv = b1[ob+j];
        unsigned long long pb = pack2(bv,bv);
#pragma unroll
        for (int q = 0; q < 4; ++q) acc[j][q] = pb;
    }
#pragma unroll 4
    for (int c2 = 0; c2 < 32; ++c2) {
        const float* base = tx + c2*512;
        ulonglong2 a0 = *(const ulonglong2*)(base + lane*4);
        ulonglong2 a1 = *(const ulonglong2*)(base + 128 + lane*4);
        ulonglong2 c0 = *(const ulonglong2*)(base + 256 + lane*4);
        ulonglong2 c1 = *(const ulonglong2*)(base + 384 + lane*4);
#pragma unroll
        for (int j = 0; j < 8; ++j) {
            ulonglong2 wp = *(const ulonglong2*)(w1d + (ob+j)*64 + c2*2);
            acc[j][0] = fma2(wp.x, a0.x, acc[j][0]);
            acc[j][1] = fma2(wp.x, a0.y, acc[j][1]);
            acc[j][2] = fma2(wp.x, a1.x, acc[j][2]);
            acc[j][3] = fma2(wp.x, a1.y, acc[j][3]);
            acc[j][0] = fma2(wp.y, c0.x, acc[j][0]);
            acc[j][1] = fma2(wp.y, c0.y, acc[j][1]);
            acc[j][2] = fma2(wp.y, c1.x, acc[j][2]);
            acc[j][3] = fma2(wp.y, c1.y, acc[j][3]);
        }
    }
#pragma unroll
    for (int j = 0; j < 8; ++j) {
        float2 u0 = unpack2(acc[j][0]), u1 = unpack2(acc[j][1]);
        float2 v0 = unpack2(acc[j][2]), v1 = unpack2(acc[j][3]);
        float4 o0 = make_float4(u0.x,u0.y,u1.x,u1.y);
        float4 o1 = make_float4(v0.x,v0.y,v1.x,v1.y);
        *(float4*)(g_x2 + (size_t)(ob+j)*PPOS + p0 + lane*4)       = o0;
        *(float4*)(g_x2 + (size_t)(ob+j)*PPOS + p0 + 128 + lane*4) = o1;
        float sm1 = ((o0.x+o0.y)+(o0.z+o0.w)) + ((o1.x+o1.y)+(o1.z+o1.w));
        float sq  = o0.x*o0.x+o0.y*o0.y+o0.z*o0.z+o0.w*o0.w
                  + o1.x*o1.x+o1.y*o1.y+o1.z*o1.z+o1.w*o1.w;
#pragma unroll
        for (int off = 16; off; off >>= 1) {
            sm1 += __shfl_down_sync(0xFFFFFFFFu, sm1, off);
            sq  += __shfl_down_sync(0xFFFFFFFFu, sq,  off);
        }
        if (lane == 0) {
            atomicAdd(&g_stats[ob+j],    sm1);
            atomicAdd(&g_stats[64+ob+j], sq);
        }
    }
}

// Generic BN fold.
__global__ void bnparam_kernel(const float* __restrict__ stats,
                               const float* __restrict__ g,
                               const float* __restrict__ beta,
                               float* __restrict__ ab, int C)
{
    int o = threadIdx.x;
    if (o < C) {
        const float invP = 1.0f / (float)PPOS;
        float mean = stats[o]   * invP;
        float var  = stats[C+o] * invP - mean*mean;
        float A = g[o] * rsqrtf(var + 1e-5f);
        ab[o]   = A;
        ab[C+o] = fmaf(-mean, A, beta[o]);
    }
}

// Layer3 (64->128) with fused BN3 stats + raw max/min pooling.
__global__ __launch_bounds__(512) void mlp3_kernel(const float* __restrict__ w2,
                                                   const float* __restrict__ b2)
{
    extern __shared__ char smraw[];
    unsigned long long* wd = (unsigned long long*)smraw;   // 8192 ull = 64KB
    float* tx = (float*)(smraw + 65536);                   // 64 x 256 = 64KB
    const int tid  = threadIdx.x;
    const int lane = tid & 31, wid = tid >> 5;
    const int ob = wid * 8;
    const int p0 = blockIdx.x * 256;

    for (int i = tid; i < 2048; i += 512) {
        float4 v = ((const float4*)w2)[i];
        wd[i*4+0] = pack2(v.x,v.x); wd[i*4+1] = pack2(v.y,v.y);
        wd[i*4+2] = pack2(v.z,v.z); wd[i*4+3] = pack2(v.w,v.w);
    }
    for (int i = tid; i < 4096; i += 512) {
        int c = i >> 6, pp = (i & 63) * 4;
        float A = g_ab[128+c], Bv = g_ab[192+c];
        float4 v = *(const float4*)(g_x2 + (size_t)c*PPOS + p0 + pp);
        float4 r;
        r.x = fmaxf(fmaf(v.x,A,Bv),0.f); r.y = fmaxf(fmaf(v.y,A,Bv),0.f);
        r.z = fmaxf(fmaf(v.z,A,Bv),0.f); r.w = fmaxf(fmaf(v.w,A,Bv),0.f);
        *(float4*)(tx + c*256 + pp) = r;
    }
    __syncthreads();

    unsigned long long acc[8][4];
#pragma unroll
    for (int j = 0; j < 8; ++j) {
        float bv = b2[ob+j];
        unsigned long long pb = pack2(bv,bv);
#pragma unroll
        for (int q = 0; q < 4; ++q) acc[j][q] = pb;
    }
#pragma unroll 4
    for (int c2 = 0; c2 < 32; ++c2) {
        const float* base = tx + c2*512;
        ulonglong2 a0 = *(const ulonglong2*)(base + lane*4);
        ulonglong2 a1 = *(const ulonglong2*)(base + 128 + lane*4);
        ulonglong2 c0 = *(const ulonglong2*)(base + 256 + lane*4);
        ulonglong2 c1 = *(const ulonglong2*)(base + 384 + lane*4);
#pragma unroll
        for (int j = 0; j < 8; ++j) {
            ulonglong2 wp = *(const ulonglong2*)(wd + (ob+j)*64 + c2*2);
            acc[j][0] = fma2(wp.x, a0.x, acc[j][0]);
            acc[j][1] = fma2(wp.x, a0.y, acc[j][1]);
            acc[j][2] = fma2(wp.x, a1.x, acc[j][2]);
            acc[j][3] = fma2(wp.x, a1.y, acc[j][3]);
            acc[j][0] = fma2(wp.y, c0.x, acc[j][0]);
            acc[j][1] = fma2(wp.y, c0.y, acc[j][1]);
            acc[j][2] = fma2(wp.y, c1.x, acc[j][2]);
            acc[j][3] = fma2(wp.y, c1.y, acc[j][3]);
        }
    }
#pragma unroll
    for (int j = 0; j < 8; ++j) {
        float2 u0 = unpack2(acc[j][0]), u1 = unpack2(acc[j][1]);
        float2 v0 = unpack2(acc[j][2]), v1 = unpack2(acc[j][3]);
        float f0 = u0.x, f1 = u0.y, f2 = u1.x, f3 = u1.y;
        float f4 = v0.x, f5 = v0.y, f6 = v1.x, f7 = v1.y;
        float sm1 = ((f0+f1)+(f2+f3)) + ((f4+f5)+(f6+f7));
        float sq  = f0*f0+f1*f1+f2*f2+f3*f3 + f4*f4+f5*f5+f6*f6+f7*f7;
#pragma unroll
        for (int off = 16; off; off >>= 1) {
            sm1 += __shfl_down_sync(0xFFFFFFFFu, sm1, off);
            sq  += __shfl_down_sync(0xFFFFFFFFu, sq,  off);
        }
        if (lane == 0) {
            atomicAdd(&g_stats[128+ob+j], sm1);
            atomicAdd(&g_stats[256+ob+j], sq);
        }
#pragma unroll
        for (int s2 = 0; s2 < 2; ++s2) {
            float a = s2 ? f4 : f0, b = s2 ? f5 : f1, c = s2 ? f6 : f2, d = s2 ? f7 : f3;
            float mx = fmaxf(fmaxf(a,b), fmaxf(c,d));
            float mn = fminf(fminf(a,b), fminf(c,d));
#pragma unroll
            for (int dlt = 1; dlt < 8; dlt <<= 1) {
                mx = fmaxf(mx, __shfl_xor_sync(0xFFFFFFFFu, mx, dlt));
                mn = fminf(mn, __shfl_xor_sync(0xFFFFFFFFu, mn, dlt));
            }
            if ((lane & 7) == 0) {
                int gid = blockIdx.x*8 + s2*4 + (lane >> 3);
                g_pmax[(ob+j)*NGRP + gid] = mx;
                g_pmin[(ob+j)*NGRP + gid] = mn;
            }
        }
    }
}

// Final: affine3+relu applied to pooled max (or min if A<0). out[b][o][s].
__global__ __launch_bounds__(256) void final_kernel(float* __restrict__ out)
{
    int t = blockIdx.x*256 + threadIdx.x;
    int o = (t >> 9) & 127;
    int b = t >> 16;
    int s = t & 511;
    int gid = b*512 + s;
    float A  = g_ab[256 + o];
    float Bv = g_ab[384 + o];
    float v = (A >= 0.0f) ? g_pmax[o*NGRP + gid] : g_pmin[o*NGRP + gid];
    out[t] = fmaxf(fmaf(v, A, Bv), 0.0f);
}

// ---------------- launch ----------------
extern "C" void kernel_launch(void* const* d_in, const int* in_sizes, int n_in,
                              void* d_out, int out_size)
{
    const float* xyz = (const float*)d_in[0];
    const float* pts = (const float*)d_in[1];
    const float* w0  = (const float*)d_in[2];
    const float* b0  = (const float*)d_in[3];
    const float* gm0 = (const float*)d_in[4];
    const float* be0 = (const float*)d_in[5];
    const float* w1  = (const float*)d_in[6];
    const float* b1  = (const float*)d_in[7];
    const float* gm1 = (const float*)d_in[8];
    const float* be1 = (const float*)d_in[9];
    const float* w2  = (const float*)d_in[10];
    const float* b2  = (const float*)d_in[11];
    const float* gm2 = (const float*)d_in[12];
    const float* be2 = (const float*)d_in[13];
    float* out = (float*)d_out;

    float *pst, *pab;
    cudaGetSymbolAddress((void**)&pst, g_stats);
    cudaGetSymbolAddress((void**)&pab, g_ab);

    cudaFuncSetAttribute(fps_kernel,     cudaFuncAttributeMaxDynamicSharedMemorySize, 49152);
    cudaFuncSetAttribute(fused12_kernel, cudaFuncAttributeMaxDynamicSharedMemorySize, 107520);
    cudaFuncSetAttribute(mlp3_kernel,    cudaFuncAttributeMaxDynamicSharedMemorySize, 131072);

    fps_kernel<<<BB, 512, 49152>>>(xyz, out);
    group_kernel<<<(BB*SS)/8, 256>>>(xyz, pts);
    bn1param_kernel<<<1, 64>>>(w0, b0, gm0, be0);

    fused12_kernel<<<PPOS/256, 256, 107520>>>(w0, w1, b1);
    bnparam_kernel<<<1, 64>>>(pst, gm1, be1, pab + 128, 64);

    mlp3_kernel<<<PPOS/256, 512, 131072>>>(w2, b2);
    bnparam_kernel<<<1, 128>>>(pst + 128, gm2, be2, pab + 256, 128);

    final_kernel<<<(BB*128*SS)/256, 256>>>(out + BB*3*SS);
}

// round 6
// speedup vs baseline: 1.7088x; 1.0062x over previous
#include <cuda_runtime.h>

#define BB 16
#define NN 4096
#define SS 512
#define NSAMP 32
#define PPOS (BB*SS*NSAMP)   // 262144 positions
#define NGRP (BB*SS)         // 8192 (b,s) groups

// ---------------- device scratch ----------------
__device__ float g_feat[6*PPOS];        // grouped features [c][p]
__device__ float g_x2[64*PPOS];         // layer2 raw conv out
__device__ float2 g_pool[128*NGRP];     // {max,min} of raw layer3 per group
__device__ float g_stats[384];          // [0..127] L2 sum/sumsq, [128..383] L3
__device__ float g_gram[27*32];         // 27 moments, line-padded (864 floats)
__device__ float4 g_new[NGRP];          // centroid x,y,z,|c|^2

// ---------------- f32x2 helpers ----------------
__device__ __forceinline__ unsigned long long fma2(unsigned long long a,
                                                   unsigned long long b,
                                                   unsigned long long c) {
    unsigned long long d;
    asm("fma.rn.f32x2 %0, %1, %2, %3;" : "=l"(d) : "l"(a), "l"(b), "l"(c));
    return d;
}
__device__ __forceinline__ unsigned long long pack2(float lo, float hi) {
    unsigned long long d;
    asm("mov.b64 %0, {%1, %2};" : "=l"(d) : "f"(lo), "f"(hi));
    return d;
}
__device__ __forceinline__ float2 unpack2(unsigned long long v) {
    float2 r;
    asm("mov.b64 {%0, %1}, %2;" : "=f"(r.x), "=f"(r.y) : "l"(v));
    return r;
}

// FPS: 1 CTA/batch, 1024 threads, 4 pts/thread, tree argmax, 1 barrier/iter.
__global__ __launch_bounds__(1024) void fps_kernel(const float* __restrict__ xyz,
                                                   float* __restrict__ out_newxyz)
{
    extern __shared__ float sh[];
    float* xs = sh; float* ys = sh + NN; float* zs = sh + 2*NN;
    __shared__ unsigned long long wkey[2][32];
    const int b = blockIdx.x;
    const int t = threadIdx.x;
    const int lane = t & 31, wid = t >> 5;
    const float* X = xyz + b*3*NN;

    if (b == 0) {   // re-zero ALL accumulator scratch every launch (replay-safe)
        if (t < 384)   g_stats[t] = 0.0f;
        if (t < 27*32) g_gram[t]  = 0.0f;
    }

    float px[4], py[4], pz[4], dist[4];
#pragma unroll
    for (int k = 0; k < 4; ++k) {
        int n = t + k*1024;
        px[k] = X[n]; py[k] = X[NN+n]; pz[k] = X[2*NN+n];
        xs[n] = px[k]; ys[n] = py[k]; zs[n] = pz[k];
        dist[k] = 1e10f;
    }
    __syncthreads();

    int far = 0;
    for (int s = 0; s < SS; ++s) {
        float cx = xs[far], cy = ys[far], cz = zs[far];
        if (t == 0) {
            out_newxyz[(b*3+0)*SS + s] = cx;
            out_newxyz[(b*3+1)*SS + s] = cy;
            out_newxyz[(b*3+2)*SS + s] = cz;
            float sn = fmaf(cz,cz,fmaf(cy,cy,cx*cx));
            g_new[b*SS+s] = make_float4(cx,cy,cz,sn);
        }
        float nd[4];
#pragma unroll
        for (int k = 0; k < 4; ++k) {
            float dx = px[k]-cx, dy = py[k]-cy, dz = pz[k]-cz;
            float d = fmaf(dz,dz,fmaf(dy,dy,dx*dx));
            nd[k] = fminf(dist[k], d);
            dist[k] = nd[k];
        }
        // tree argmax, ties -> lowest index (strict > since indices ascend with k)
        float m0 = nd[0]; int j0 = t;
        { bool c = nd[1] > m0; m0 = c ? nd[1] : m0; j0 = c ? t+1024 : j0; }
        float m1 = nd[2]; int j1 = t+2048;
        { bool c = nd[3] > m1; m1 = c ? nd[3] : m1; j1 = c ? t+3072 : j1; }
        bool c2 = m1 > m0;
        float bd = c2 ? m1 : m0; int bi = c2 ? j1 : j0;

        unsigned db = __float_as_uint(bd);   // bd >= 0: bits order-preserving
        unsigned wm = __reduce_max_sync(0xFFFFFFFFu, db);
        unsigned lo = __reduce_max_sync(0xFFFFFFFFu, (db == wm) ? ~(unsigned)bi : 0u);
        if (lane == 0) wkey[s & 1][wid] = ((unsigned long long)wm << 32) | lo;
        __syncthreads();
        unsigned long long k2 = wkey[s & 1][lane];
        unsigned hi = (unsigned)(k2 >> 32), l2 = (unsigned)k2;
        unsigned m2 = __reduce_max_sync(0xFFFFFFFFu, hi);
        unsigned lw = __reduce_max_sync(0xFFFFFFFFu, (hi == m2) ? l2 : 0u);
        far = (int)(~lw);
    }
}

// Ball query + gather + fused 27-moment accumulation. One warp per centroid.
__global__ __launch_bounds__(256) void group_kernel(const float* __restrict__ xyz,
                                                    const float* __restrict__ pts)
{
    __shared__ int sel[8][NSAMP];
    __shared__ float red[27];
    const int lane = threadIdx.x & 31, w = threadIdx.x >> 5;
    const int tid = threadIdx.x;
    if (tid < 27) red[tid] = 0.0f;
    __syncthreads();

    const int id = blockIdx.x*8 + w;
    const int b = id >> 9;
    const float4 c4 = g_new[id];
    const float* X = xyz + b*3*NN;
    const float* Q = pts + b*3*NN;
    const float R2 = (float)(0.4*0.4);

    int cnt = 0;
    for (int base = 0; base < NN && cnt < NSAMP; base += 32) {
        int n = base + lane;
        float x = X[n], y = X[NN+n], z = X[2*NN+n];
        float sx  = fmaf(z,z,fmaf(y,y,x*x));
        float dot = fmaf(z,c4.z,fmaf(y,c4.y,x*c4.x));
        float sq  = (c4.w + sx) - 2.0f*dot;
        bool pred = (sq <= R2);
        unsigned m = __ballot_sync(0xFFFFFFFFu, pred);
        if (pred) {
            int pos = cnt + __popc(m & ((1u << lane) - 1u));
            if (pos < NSAMP) sel[w][pos] = n;
        }
        cnt += __popc(m);
    }
    __syncwarp();
    int total = cnt < NSAMP ? cnt : NSAMP;
    int idx = sel[w][lane < total ? lane : 0];

    float f[6];
    f[0] = X[idx]      - c4.x;
    f[1] = X[NN+idx]   - c4.y;
    f[2] = X[2*NN+idx] - c4.z;
    f[3] = Q[idx];
    f[4] = Q[NN+idx];
    f[5] = Q[2*NN+idx];

    int p = id*NSAMP + lane;
#pragma unroll
    for (int c = 0; c < 6; ++c) g_feat[c*PPOS + p] = f[c];

    float v[27];
#pragma unroll
    for (int c = 0; c < 6; ++c) v[c] = f[c];
    {
        int k = 6;
#pragma unroll
        for (int i = 0; i < 6; ++i)
#pragma unroll
            for (int j = i; j < 6; ++j) { v[k] = f[i]*f[j]; ++k; }
    }
#pragma unroll
    for (int off = 16; off; off >>= 1)
#pragma unroll
        for (int i = 0; i < 27; ++i)
            v[i] += __shfl_down_sync(0xFFFFFFFFu, v[i], off);
    if (lane == 0)
#pragma unroll
        for (int i = 0; i < 27; ++i) atomicAdd(&red[i], v[i]);
    __syncthreads();
    if (tid < 27) atomicAdd(&g_gram[tid*32], red[tid]);
}

// Fused layer1+layer2 with inline analytic BN1.
__global__ __launch_bounds__(256,2) void fused12_kernel(const float* __restrict__ w0,
                                                        const float* __restrict__ b0,
                                                        const float* __restrict__ g0,
                                                        const float* __restrict__ beta0,
                                                        const float* __restrict__ w1,
                                                        const float* __restrict__ b1)
{
    extern __shared__ char smraw[];
    unsigned long long* w0d = (unsigned long long*)smraw;            // 384 ull
    unsigned long long* w1d = (unsigned long long*)(smraw + 3072);   // 4096 ull
    float* sab = (float*)(smraw + 35840);                            // 128 (BN1 A/B)
    float* tf  = (float*)(smraw + 36352);                            // 6 x 256
    float* tx  = (float*)(smraw + 42496);                            // 64 x 256
    const int tid  = threadIdx.x;
    const int lane = tid & 31, wid = tid >> 5;
    const int ob = wid * 8;
    const int p0 = blockIdx.x * 256;

    // inline analytic BN1 (redundant per CTA; tiny)
    if (tid < 64) {
        const int o = tid;
        float w[6];
#pragma unroll
        for (int c = 0; c < 6; ++c) w[c] = w0[o*6+c];
        float wS = 0.0f;
#pragma unroll
        for (int c = 0; c < 6; ++c) wS = fmaf(w[c], g_gram[c*32], wS);
        float quad = 0.0f; int idx = 6;
#pragma unroll
        for (int i = 0; i < 6; ++i)
#pragma unroll
            for (int j = i; j < 6; ++j) {
                float coef = (i == j) ? 1.0f : 2.0f;
                quad = fmaf(coef * w[i] * w[j], g_gram[idx*32], quad);
                ++idx;
            }
        float bo = b0[o];
        const float invP = 1.0f / (float)PPOS;
        float m   = fmaf(wS, invP, bo);
        float Ex2 = quad*invP + 2.0f*bo*wS*invP + bo*bo;
        float A = g0[o] * rsqrtf(Ex2 - m*m + 1e-5f);
        sab[o]    = A;
        sab[64+o] = fmaf(bo - m, A, beta0[o]);
    }

    for (int i = tid; i < 384; i += 256) { float v = w0[i]; w0d[i] = pack2(v,v); }
    for (int i = tid; i < 1024; i += 256) {
        float4 v = ((const float4*)w1)[i];
        w1d[i*4+0] = pack2(v.x,v.x); w1d[i*4+1] = pack2(v.y,v.y);
        w1d[i*4+2] = pack2(v.z,v.z); w1d[i*4+3] = pack2(v.w,v.w);
    }
    for (int i = tid; i < 384; i += 256) {
        int c = i >> 6, pp = (i & 63) * 4;
        *(float4*)(tf + c*256 + pp) = *(const float4*)(g_feat + c*PPOS + p0 + pp);
    }
    __syncthreads();

    // ---- stage A: 6 -> 64 ----
    {
        unsigned long long a[8][4];
#pragma unroll
        for (int j = 0; j < 8; ++j)
#pragma unroll
            for (int q = 0; q < 4; ++q) a[j][q] = 0ull;
#pragma unroll
        for (int c = 0; c < 6; ++c) {
            ulonglong2 iv0 = *(const ulonglong2*)(tf + c*256 + lane*4);
            ulonglong2 iv1 = *(const ulonglong2*)(tf + c*256 + 128 + lane*4);
#pragma unroll
            for (int j = 0; j < 8; ++j) {
                unsigned long long wv = w0d[(ob+j)*6 + c];
                a[j][0] = fma2(wv, iv0.x, a[j][0]);
                a[j][1] = fma2(wv, iv0.y, a[j][1]);
                a[j][2] = fma2(wv, iv1.x, a[j][2]);
                a[j][3] = fma2(wv, iv1.y, a[j][3]);
            }
        }
#pragma unroll
        for (int j = 0; j < 8; ++j) {
            float A = sab[ob+j], Bv = sab[64+ob+j];
#pragma unroll
            for (int s2 = 0; s2 < 2; ++s2) {
                float2 u = unpack2(a[j][s2*2+0]);
                float2 v = unpack2(a[j][s2*2+1]);
                float4 o4;
                o4.x = fmaxf(fmaf(u.x,A,Bv),0.f);
                o4.y = fmaxf(fmaf(u.y,A,Bv),0.f);
                o4.z = fmaxf(fmaf(v.x,A,Bv),0.f);
                o4.w = fmaxf(fmaf(v.y,A,Bv),0.f);
                *(float4*)(tx + (ob+j)*256 + s2*128 + lane*4) = o4;
            }
        }
    }
    __syncthreads();

    // ---- stage B: 64 -> 64 ----
    unsigned long long acc[8][4];
#pragma unroll
    for (int j = 0; j < 8; ++j) {
        float bv = b1[ob+j];
        unsigned long long pb = pack2(bv,bv);
#pragma unroll
        for (int q = 0; q < 4; ++q) acc[j][q] = pb;
    }
#pragma unroll 4
    for (int c2 = 0; c2 < 32; ++c2) {
        const float* base = tx + c2*512;
        ulonglong2 a0 = *(const ulonglong2*)(base + lane*4);
        ulonglong2 a1 = *(const ulonglong2*)(base + 128 + lane*4);
        ulonglong2 c0 = *(const ulonglong2*)(base + 256 + lane*4);
        ulonglong2 c1 = *(const ulonglong2*)(base + 384 + lane*4);
#pragma unroll
        for (int j = 0; j < 8; ++j) {
            ulonglong2 wp = *(const ulonglong2*)(w1d + (ob+j)*64 + c2*2);
            acc[j][0] = fma2(wp.x, a0.x, acc[j][0]);
            acc[j][1] = fma2(wp.x, a0.y, acc[j][1]);
            acc[j][2] = fma2(wp.x, a1.x, acc[j][2]);
            acc[j][3] = fma2(wp.x, a1.y, acc[j][3]);
            acc[j][0] = fma2(wp.y, c0.x, acc[j][0]);
            acc[j][1] = fma2(wp.y, c0.y, acc[j][1]);
            acc[j][2] = fma2(wp.y, c1.x, acc[j][2]);
            acc[j][3] = fma2(wp.y, c1.y, acc[j][3]);
        }
    }
#pragma unroll
    for (int j = 0; j < 8; ++j) {
        float2 u0 = unpack2(acc[j][0]), u1 = unpack2(acc[j][1]);
        float2 v0 = unpack2(acc[j][2]), v1 = unpack2(acc[j][3]);
        float4 o0 = make_float4(u0.x,u0.y,u1.x,u1.y);
        float4 o1 = make_float4(v0.x,v0.y,v1.x,v1.y);
        *(float4*)(g_x2 + (size_t)(ob+j)*PPOS + p0 + lane*4)       = o0;
        *(float4*)(g_x2 + (size_t)(ob+j)*PPOS + p0 + 128 + lane*4) = o1;
        float sm1 = ((o0.x+o0.y)+(o0.z+o0.w)) + ((o1.x+o1.y)+(o1.z+o1.w));
        float sq  = o0.x*o0.x+o0.y*o0.y+o0.z*o0.z+o0.w*o0.w
                  + o1.x*o1.x+o1.y*o1.y+o1.z*o1.z+o1.w*o1.w;
#pragma unroll
        for (int off = 16; off; off >>= 1) {
            sm1 += __shfl_down_sync(0xFFFFFFFFu, sm1, off);
            sq  += __shfl_down_sync(0xFFFFFFFFu, sq,  off);
        }
        if (lane == 0) {
            atomicAdd(&g_stats[ob+j],    sm1);
            atomicAdd(&g_stats[64+ob+j], sq);
        }
    }
}

// Layer3 (64->128) with inline BN2 fold, fused BN3 stats + {max,min} pooling.
__global__ __launch_bounds__(512) void mlp3_kernel(const float* __restrict__ w2,
                                                   const float* __restrict__ b2,
                                                   const float* __restrict__ g1,
                                                   const float* __restrict__ beta1)
{
    extern __shared__ char smraw[];
    unsigned long long* wd = (unsigned long long*)smraw;   // 8192 ull = 64KB
    float* sab = (float*)(smraw + 65536);                  // 128 (BN2 A/B)
    float* tx  = (float*)(smraw + 66048);                  // 64 x 256 = 64KB
    const int tid  = threadIdx.x;
    const int lane = tid & 31, wid = tid >> 5;
    const int ob = wid * 8;
    const int p0 = blockIdx.x * 256;

    if (tid < 64) {
        const float invP = 1.0f / (float)PPOS;
        float mean = g_stats[tid]    * invP;
        float var  = g_stats[64+tid] * invP - mean*mean;
        float A = g1[tid] * rsqrtf(var + 1e-5f);
        sab[tid]    = A;
        sab[64+tid] = fmaf(-mean, A, beta1[tid]);
    }
    for (int i = tid; i < 2048; i += 512) {
        float4 v = ((const float4*)w2)[i];
        wd[i*4+0] = pack2(v.x,v.x); wd[i*4+1] = pack2(v.y,v.y);
        wd[i*4+2] = pack2(v.z,v.z); wd[i*4+3] = pack2(v.w,v.w);
    }
    __syncthreads();
    for (int i = tid; i < 4096; i += 512) {
        int c = i >> 6, pp = (i & 63) * 4;
        float A = sab[c], Bv = sab[64+c];
        float4 v = *(const float4*)(g_x2 + (size_t)c*PPOS + p0 + pp);
        float4 r;
        r.x = fmaxf(fmaf(v.x,A,Bv),0.f); r.y = fmaxf(fmaf(v.y,A,Bv),0.f);
        r.z = fmaxf(fmaf(v.z,A,Bv),0.f); r.w = fmaxf(fmaf(v.w,A,Bv),0.f);
        *(float4*)(tx + c*256 + pp) = r;
    }
    __syncthreads();

    unsigned long long acc[8][4];
#pragma unroll
    for (int j = 0; j < 8; ++j) {
        float bv = b2[ob+j];
        unsigned long long pb = pack2(bv,bv);
#pragma unroll
        for (int q = 0; q < 4; ++q) acc[j][q] = pb;
    }
#pragma unroll 4
    for (int c2 = 0; c2 < 32; ++c2) {
        const float* base = tx + c2*512;
        ulonglong2 a0 = *(const ulonglong2*)(base + lane*4);
        ulonglong2 a1 = *(const ulonglong2*)(base + 128 + lane*4);
        ulonglong2 c0 = *(const ulonglong2*)(base + 256 + lane*4);
        ulonglong2 c1 = *(const ulonglong2*)(base + 384 + lane*4);
#pragma unroll
        for (int j = 0; j < 8; ++j) {
            ulonglong2 wp = *(const ulonglong2*)(wd + (ob+j)*64 + c2*2);
            acc[j][0] = fma2(wp.x, a0.x, acc[j][0]);
            acc[j][1] = fma2(wp.x, a0.y, acc[j][1]);
            acc[j][2] = fma2(wp.x, a1.x, acc[j][2]);
            acc[j][3] = fma2(wp.x, a1.y, acc[j][3]);
            acc[j][0] = fma2(wp.y, c0.x, acc[j][0]);
            acc[j][1] = fma2(wp.y, c0.y, acc[j][1]);
            acc[j][2] = fma2(wp.y, c1.x, acc[j][2]);
            acc[j][3] = fma2(wp.y, c1.y, acc[j][3]);
        }
    }
#pragma unroll
    for (int j = 0; j < 8; ++j) {
        float2 u0 = unpack2(acc[j][0]), u1 = unpack2(acc[j][1]);
        float2 v0 = unpack2(acc[j][2]), v1 = unpack2(acc[j][3]);
        float f0 = u0.x, f1 = u0.y, f2 = u1.x, f3 = u1.y;
        float f4 = v0.x, f5 = v0.y, f6 = v1.x, f7 = v1.y;
        float sm1 = ((f0+f1)+(f2+f3)) + ((f4+f5)+(f6+f7));
        float sq  = f0*f0+f1*f1+f2*f2+f3*f3 + f4*f4+f5*f5+f6*f6+f7*f7;
#pragma unroll
        for (int off = 16; off; off >>= 1) {
            sm1 += __shfl_down_sync(0xFFFFFFFFu, sm1, off);
            sq  += __shfl_down_sync(0xFFFFFFFFu, sq,  off);
        }
        if (lane == 0) {
            atomicAdd(&g_stats[128+ob+j], sm1);
            atomicAdd(&g_stats[256+ob+j], sq);
        }
#pragma unroll
        for (int s2 = 0; s2 < 2; ++s2) {
            float a = s2 ? f4 : f0, b = s2 ? f5 : f1, c = s2 ? f6 : f2, d = s2 ? f7 : f3;
            float mx = fmaxf(fmaxf(a,b), fmaxf(c,d));
            float mn = fminf(fminf(a,b), fminf(c,d));
#pragma unroll
            for (int dlt = 1; dlt < 8; dlt <<= 1) {
                mx = fmaxf(mx, __shfl_xor_sync(0xFFFFFFFFu, mx, dlt));
                mn = fminf(mn, __shfl_xor_sync(0xFFFFFFFFu, mn, dlt));
            }
            if ((lane & 7) == 0) {
                int gid = blockIdx.x*8 + s2*4 + (lane >> 3);
                g_pool[(ob+j)*NGRP + gid] = make_float2(mx, mn);
            }
        }
    }
}

// Final: inline BN3 fold + affine+relu on pooled max/min. One CTA per (b,o).
__global__ __launch_bounds__(256) void final_kernel(float* __restrict__ out,
                                                    const float* __restrict__ g2,
                                                    const float* __restrict__ beta2)
{
    __shared__ float sA, sB;
    const int o = blockIdx.x & 127;
    const int b = blockIdx.x >> 7;
    if (threadIdx.x == 0) {
        const float invP = 1.0f / (float)PPOS;
        float mean = g_stats[128+o] * invP;
        float var  = g_stats[256+o] * invP - mean*mean;
        float A = g2[o] * rsqrtf(var + 1e-5f);
        sA = A; sB = fmaf(-mean, A, beta2[o]);
    }
    __syncthreads();
    float A = sA, Bv = sB;
    int s = threadIdx.x * 2;
    float2 p0 = g_pool[o*NGRP + b*SS + s];
    float2 p1 = g_pool[o*NGRP + b*SS + s + 1];
    float v0 = (A >= 0.0f) ? p0.x : p0.y;
    float v1 = (A >= 0.0f) ? p1.x : p1.y;
    float2 r;
    r.x = fmaxf(fmaf(v0, A, Bv), 0.0f);
    r.y = fmaxf(fmaf(v1, A, Bv), 0.0f);
    *(float2*)(out + ((b*128 + o) << 9) + s) = r;
}

// ---------------- launch ----------------
extern "C" void kernel_launch(void* const* d_in, const int* in_sizes, int n_in,
                              void* d_out, int out_size)
{
    const float* xyz = (const float*)d_in[0];
    const float* pts = (const float*)d_in[1];
    const float* w0  = (const float*)d_in[2];
    const float* b0  = (const float*)d_in[3];
    const float* gm0 = (const float*)d_in[4];
    const float* be0 = (const float*)d_in[5];
    const float* w1  = (const float*)d_in[6];
    const float* b1  = (const float*)d_in[7];
    const float* gm1 = (const float*)d_in[8];
    const float* be1 = (const float*)d_in[9];
    const float* w2  = (const float*)d_in[10];
    const float* b2  = (const float*)d_in[11];
    const float* gm2 = (const float*)d_in[12];
    const float* be2 = (const float*)d_in[13];
    float* out = (float*)d_out;

    cudaFuncSetAttribute(fps_kernel,     cudaFuncAttributeMaxDynamicSharedMemorySize, 49152);
    cudaFuncSetAttribute(fused12_kernel, cudaFuncAttributeMaxDynamicSharedMemorySize, 108032);
    cudaFuncSetAttribute(mlp3_kernel,    cudaFuncAttributeMaxDynamicSharedMemorySize, 131584);

    fps_kernel<<<BB, 1024, 49152>>>(xyz, out);
    group_kernel<<<(BB*SS)/8, 256>>>(xyz, pts);
    fused12_kernel<<<PPOS/256, 256, 108032>>>(w0, b0, gm0, be0, w1, b1);
    mlp3_kernel<<<PPOS/256, 512, 131584>>>(w2, b2, gm1, be1);
    final_kernel<<<BB*128, 256>>>(out + BB*3*SS, gm2, be2);
}